// round 15
// baseline (speedup 1.0000x reference)
#include <cuda_runtime.h>
#include <math.h>

#define B 4
#define N 20000
#define M 1024
#define PL 50
#define L_CAP 192   // per-keypoint list capacity (>> max Voronoi occupancy)

// Scratch (allocation-free rule: __device__ globals, zero-initialized at load).
// Pipeline is self-resetting: k_select zeroes counters/sums every launch.
__device__ int    g_p2n[B * N];
__device__ int    g_count[B * M];
__device__ float  g_sumx[B * M];
__device__ float  g_sumy[B * M];
__device__ float  g_sumz[B * M];
__device__ int    g_lidx[B * M * L_CAP];
__device__ float  g_ldst[B * M * L_CAP];
__device__ float  g_partA[512];
__device__ float  g_partW[512];
__device__ int    g_doneGrp[32];   // two-level completion ticket: 16 arrivals each
__device__ int    g_doneRoot;      // 32 arrivals

__device__ __forceinline__ unsigned long long pack2(float lo, float hi) {
    unsigned long long d;
    asm("mov.b64 %0, {%1, %2};" : "=l"(d) : "f"(lo), "f"(hi));
    return d;
}

// ---------------- k_assign: per-point argmin over M keypoints ----------------
// TWO points per thread x TWO m's packed per f32x2 op: one pair of broadcast
// LDS.128 feeds both points' FFMA2 chains (10 issue slots per point-m-pair
// vs 12 for the 1-point version). Each point keeps its own even/odd min
// chains; merge semantics identical to the proven round-10 version.
#define K1_THREADS 64
#define PTS_PER_BLK (K1_THREADS * 2)                      // 128
#define K1_BLKS ((N + PTS_PER_BLK - 1) / PTS_PER_BLK)     // 157
#define MP (M / 2)                                        // 512 m-pairs

__global__ __launch_bounds__(K1_THREADS) void k_assign(
        const float* __restrict__ pts,
        const float* __restrict__ kp) {
    // sA[mp] = {pack2(kx_e,kx_o), pack2(ky_e,ky_o)}
    // sB[mp] = {pack2(kz_e,kz_o), pack2(kw_e,kw_o)}, kw = 0.5*|k|^2
    __shared__ ulonglong2 sA[MP];
    __shared__ ulonglong2 sB[MP];

    const int b = blockIdx.y;
    const float* kpb = kp + (size_t)b * M * 3;
    for (int mp = threadIdx.x; mp < MP; mp += K1_THREADS) {
        int me = 2 * mp, mo = 2 * mp + 1;
        float ex = kpb[me * 3 + 0], ey = kpb[me * 3 + 1], ez = kpb[me * 3 + 2];
        float ox = kpb[mo * 3 + 0], oy = kpb[mo * 3 + 1], oz = kpb[mo * 3 + 2];
        float ew = 0.5f * (ex * ex + ey * ey + ez * ez);
        float ow_ = 0.5f * (ox * ox + oy * oy + oz * oz);
        ulonglong2 a, c;
        a.x = pack2(ex, ox); a.y = pack2(ey, oy);
        c.x = pack2(ez, oz); c.y = pack2(ew, ow_);
        sA[mp] = a;
        sB[mp] = c;
    }
    __syncthreads();

    const int p0 = blockIdx.x * PTS_PER_BLK + threadIdx.x;
    const int p1 = p0 + K1_THREADS;
    float x0 = 0.f, y0 = 0.f, z0 = 0.f, x1 = 0.f, y1 = 0.f, z1 = 0.f;
    if (p0 < N) {
        const float* q = pts + ((size_t)b * N + p0) * 3;
        x0 = q[0]; y0 = q[1]; z0 = q[2];
    }
    if (p1 < N) {
        const float* q = pts + ((size_t)b * N + p1) * 3;
        x1 = q[0]; y1 = q[1]; z1 = q[2];
    }
    const unsigned long long nx20 = pack2(-x0, -x0);
    const unsigned long long ny20 = pack2(-y0, -y0);
    const unsigned long long nz20 = pack2(-z0, -z0);
    const unsigned long long nx21 = pack2(-x1, -x1);
    const unsigned long long ny21 = pack2(-y1, -y1);
    const unsigned long long nz21 = pack2(-z1, -z1);

    float bve0 = INFINITY, bvo0 = INFINITY, bve1 = INFINITY, bvo1 = INFINITY;
    int bme0 = 0, bmo0 = 0, bme1 = 0, bmo1 = 0;

#pragma unroll 8
    for (int mp = 0; mp < MP; mp++) {
        ulonglong2 a = sA[mp];
        ulonglong2 c = sB[mp];
        unsigned long long w0, w1;
        // v = 0.5|k|^2 - k.p  (monotone in true sq-dist for a fixed point)
        asm("fma.rn.f32x2 %0, %1, %2, %3;" : "=l"(w0) : "l"(c.x), "l"(nz20), "l"(c.y));
        asm("fma.rn.f32x2 %0, %1, %2, %3;" : "=l"(w1) : "l"(c.x), "l"(nz21), "l"(c.y));
        asm("fma.rn.f32x2 %0, %1, %2, %3;" : "=l"(w0) : "l"(a.y), "l"(ny20), "l"(w0));
        asm("fma.rn.f32x2 %0, %1, %2, %3;" : "=l"(w1) : "l"(a.y), "l"(ny21), "l"(w1));
        asm("fma.rn.f32x2 %0, %1, %2, %3;" : "=l"(w0) : "l"(a.x), "l"(nx20), "l"(w0));
        asm("fma.rn.f32x2 %0, %1, %2, %3;" : "=l"(w1) : "l"(a.x), "l"(nx21), "l"(w1));
        float v00, v01, v10, v11;
        asm("mov.b64 {%0, %1}, %2;" : "=f"(v00), "=f"(v01) : "l"(w0));
        asm("mov.b64 {%0, %1}, %2;" : "=f"(v10), "=f"(v11) : "l"(w1));
        // strict <: keeps FIRST minimum within each chain (ascending m).
        bool a0 = v00 < bve0; bme0 = a0 ? mp : bme0; bve0 = fminf(bve0, v00);
        bool b0 = v01 < bvo0; bmo0 = b0 ? mp : bmo0; bvo0 = fminf(bvo0, v01);
        bool a1 = v10 < bve1; bme1 = a1 ? mp : bme1; bve1 = fminf(bve1, v10);
        bool b1 = v11 < bvo1; bmo1 = b1 ? mp : bmo1; bvo1 = fminf(bvo1, v11);
    }

    // Epilogue per point. Merge: odd wins only if strictly smaller, or equal
    // with smaller m (2*bmo+1 < 2*bme only if bmo < bme).
#pragma unroll
    for (int j = 0; j < 2; j++) {
        int p = j ? p1 : p0;
        if (p >= N) continue;
        float x = j ? x1 : x0, y = j ? y1 : y0, z = j ? z1 : z0;
        float bve = j ? bve1 : bve0, bvo = j ? bvo1 : bvo0;
        int bme = j ? bme1 : bme0, bmo = j ? bmo1 : bmo0;

        int me = 2 * bme, mo = 2 * bmo + 1;
        bool ow2 = (bvo < bve) || (bvo == bve && mo < me);
        float bestv = ow2 ? bvo : bve;
        int bestm = ow2 ? mo : me;

        int gi = b * N + p;
        int bm = b * M + bestm;
        float pp = x * x + y * y + z * z;
        float dist = fmaf(2.0f, bestv, pp);      // true squared distance
        g_p2n[gi] = bestm;
        // coordinate sums (no-return atomics -> RED.ADD)
        atomicAdd(&g_sumx[bm], x);
        atomicAdd(&g_sumy[bm], y);
        atomicAdd(&g_sumz[bm], z);
        int pos = atomicAdd(&g_count[bm], 1);
        if (pos < L_CAP) {
            g_lidx[(size_t)bm * L_CAP + pos] = p;
            g_ldst[(size_t)bm * L_CAP + pos] = dist;
        }
    }
}

// ---------------- k_select: one WARP per (b, m), fused final reduce ---------
#define SEL_THREADS 256
#define SEL_WARPS (SEL_THREADS / 32)      // 8
#define SEL_BLOCKS (B * M / SEL_WARPS)    // 512
#define SLOTS (L_CAP / 32)                // 6 keys per lane

__global__ __launch_bounds__(SEL_THREADS) void k_select(
        const float* __restrict__ pts,
        const float* __restrict__ kpw,
        const float* __restrict__ pose,
        const float* __restrict__ ow,
        float* __restrict__ out) {
    __shared__ float s_a[SEL_WARPS];
    __shared__ float s_w[SEL_WARPS];
    __shared__ int s_last;

    int wg = (blockIdx.x * SEL_THREADS + threadIdx.x) >> 5;   // global warp id
    int wid = threadIdx.x >> 5;
    int lane = threadIdx.x & 31;
    int b = wg / M;
    int m = wg - b * M;
    int i = wg;

    const float* ptsb = pts + (size_t)b * N * 3;
    const int* p2nb = g_p2n + (size_t)b * N;

    // Independent loads up front (all L2-resident from k_assign's writes).
    int c = g_count[i];
    float ssx = g_sumx[i];
    float ssy = g_sumy[i];
    float ssz = g_sumz[i];
    int pv = p2nb[lane];               // prefetch first filler window

    if (lane == 0) {                   // self-reset for next replay
        g_count[i] = 0;
        g_sumx[i] = 0.f; g_sumy[i] = 0.f; g_sumz[i] = 0.f;
    }

    float sx = 0.f, sy = 0.f, sz = 0.f;
    int fill;

    if (c <= PL) {
        // Sum already computed by k_assign's RED.ADD — no gather needed.
        if (lane == 0) { sx = ssx; sy = ssy; sz = ssz; }
        fill = PL - c;
    } else {
        // RANK selection: key = (enc(dist)<<32)|idx is unique => total order
        // => rank(k) = #{k' < k}; rank < 50 is EXACTLY the stable top_k set.
        const int* lidx = g_lidx + (size_t)i * L_CAP;
        const float* ldst = g_ldst + (size_t)i * L_CAP;
        int cc = min(c, L_CAP);
        int su = (cc + 31) >> 5;       // slot rounds holding real keys

        unsigned long long ks[SLOTS];
#pragma unroll
        for (int t = 0; t < SLOTS; t++) {
            int j = lane + 32 * t;
            unsigned long long key = ~0ull;         // sentinel = +inf
            if (j < cc) {
                float d = ldst[j];
                unsigned u = __float_as_uint(d);
                unsigned enc = (u & 0x80000000u) ? ~u : (u | 0x80000000u);
                key = ((unsigned long long)enc << 32) | (unsigned)lidx[j];
            }
            ks[t] = key;
        }

        unsigned cnt[SLOTS] = {0, 0, 0, 0, 0, 0};
        for (int t2 = 0; t2 < su; t2++) {
            unsigned long long kslot = ks[t2];
#pragma unroll 4
            for (int src = 0; src < 32; src++) {
                unsigned long long kk =
                    __shfl_sync(0xffffffffu, kslot, src);
#pragma unroll
                for (int t = 0; t < SLOTS; t++) cnt[t] += (kk < ks[t]);
            }
        }

        // Gather selected points (exactly 50 across the warp, <=6 per lane).
#pragma unroll
        for (int t = 0; t < SLOTS; t++) {
            if (cnt[t] < PL) {
                unsigned idx = (unsigned)ks[t];
                const float* q = &ptsb[(size_t)idx * 3];
                sx += q[0]; sy += q[1]; sz += q[2];
            }
        }
        fill = 0;
    }

    // Fillers: first (50 - c) point indices with p2n != m (FAR pad, stable
    // tie-break = ascending index). Warp-cooperative ballot sweep.
    int n0 = 0;
    while (fill > 0) {
        int n = n0 + lane;                 // n stays far below N (fill <= 50)
        int pn = (n0 == 0) ? pv : p2nb[n];
        bool ok = (pn != m);
        unsigned msk = __ballot_sync(0xffffffffu, ok);
        int rank = __popc(msk & ((1u << lane) - 1u));
        if (ok && rank < fill) {
            const float* q = &ptsb[(size_t)n * 3];
            sx += q[0]; sy += q[1]; sz += q[2];
        }
        fill -= min(fill, __popc(msk));
        n0 += 32;
    }

    // Warp reduce
#pragma unroll
    for (int off = 16; off; off >>= 1) {
        sx += __shfl_xor_sync(0xffffffffu, sx, off);
        sy += __shfl_xor_sync(0xffffffffu, sy, off);
        sz += __shfl_xor_sync(0xffffffffu, sz, off);
    }

    if (lane == 0) {
        // mean(R p + t) = R mean(p) + t
        const float* P = pose + b * 16;
        float mx = sx * (1.0f / PL), my = sy * (1.0f / PL), mz = sz * (1.0f / PL);
        float ex = P[0] * mx + P[1] * my + P[2]  * mz + P[3]  - kpw[i * 3 + 0];
        float ey = P[4] * mx + P[5] * my + P[6]  * mz + P[7]  - kpw[i * 3 + 1];
        float ez = P[8] * mx + P[9] * my + P[10] * mz + P[11] - kpw[i * 3 + 2];
        float w = ow[i];
        s_a[wid] = w * (fabsf(ex) + fabsf(ey) + fabsf(ez));
        s_w[wid] = w;
    }
    __syncthreads();

    // Per-block partial store, then a TWO-LEVEL completion ticket:
    // 512 same-address atomics -> 32 group counters (16 arrivals each, spread
    // across LTS slices) + 1 root counter (32 arrivals). Release chain:
    // partial stores -> fence -> group atomic -> (group-last) root atomic.
    if (threadIdx.x == 0) {
        float ba = 0.f, bw = 0.f;
#pragma unroll
        for (int k = 0; k < SEL_WARPS; k++) { ba += s_a[k]; bw += s_w[k]; }
        g_partA[blockIdx.x] = ba;
        g_partW[blockIdx.x] = bw;
        __threadfence();
        s_last = 0;
        int grp = blockIdx.x >> 4;                   // 32 groups of 16
        int t = atomicAdd(&g_doneGrp[grp], 1);
        if (t == 15) {
            g_doneGrp[grp] = 0;                      // reset for next replay
            int t2 = atomicAdd(&g_doneRoot, 1);
            s_last = (t2 == 31);
        }
    }
    __syncthreads();

    if (s_last) {
        __threadfence();
        float a = 0.f, w = 0.f;
        for (int k = threadIdx.x; k < SEL_BLOCKS; k += SEL_THREADS) {
            a += g_partA[k];
            w += g_partW[k];
        }
#pragma unroll
        for (int off = 16; off; off >>= 1) {
            a += __shfl_xor_sync(0xffffffffu, a, off);
            w += __shfl_xor_sync(0xffffffffu, w, off);
        }
        if (lane == 0) { s_a[wid] = a; s_w[wid] = w; }
        __syncthreads();
        if (threadIdx.x == 0) {
            double A = 0.0, W = 0.0;
#pragma unroll
            for (int k = 0; k < SEL_WARPS; k++) { A += s_a[k]; W += s_w[k]; }
            if (W < 1e-6) W = 1e-6;
            out[0] = (float)(A / W);
            g_doneRoot = 0;             // self-reset for next replay
            __threadfence();
        }
    }
}

extern "C" void kernel_launch(void* const* d_in, const int* in_sizes, int n_in,
                              void* d_out, int out_size) {
    const float* pts  = (const float*)d_in[0];  // (B, N, 3)
    const float* kp   = (const float*)d_in[1];  // (B, M, 3)
    const float* kpw  = (const float*)d_in[2];  // (B, M, 3)
    const float* pose = (const float*)d_in[3];  // (B, 4, 4)
    const float* ow   = (const float*)d_in[4];  // (B, M)
    float* out = (float*)d_out;

    dim3 g1(K1_BLKS, B);
    k_assign<<<g1, K1_THREADS>>>(pts, kp);

    k_select<<<SEL_BLOCKS, SEL_THREADS>>>(pts, kpw, pose, ow, out);
}

// round 17
// speedup vs baseline: 1.6087x; 1.6087x over previous
#include <cuda_runtime.h>
#include <math.h>

#define B 4
#define N 20000
#define M 1024
#define PL 50
#define L_CAP 192   // per-keypoint list capacity (>> max Voronoi occupancy)

// Scratch (allocation-free rule: __device__ globals, zero-initialized at load).
// Pipeline is self-resetting: k_select zeroes counters/sums every launch.
__device__ int    g_p2n[B * N];
__device__ int    g_count[B * M];
__device__ float  g_sumx[B * M];
__device__ float  g_sumy[B * M];
__device__ float  g_sumz[B * M];
__device__ int    g_lidx[B * M * L_CAP];
__device__ float  g_ldst[B * M * L_CAP];
__device__ float4 g_pref[B * 64];  // S[k] = sum of first k points (k <= PL)
__device__ float  g_partA[512];
__device__ float  g_partW[512];
__device__ int    g_done;

__device__ __forceinline__ unsigned long long pack2(float lo, float hi) {
    unsigned long long d;
    asm("mov.b64 %0, {%1, %2};" : "=l"(d) : "f"(lo), "f"(hi));
    return d;
}

// ---------------- k_assign: per-point argmin over M keypoints ----------------
// ROUND-10/14 VERSION (best measured): one point per thread, TWO m's packed
// per f32x2 op (even/odd min chains), single pass. Epilogue: per-keypoint
// coordinate sums via no-return float atomics (RED.ADD).
// Block 0 of each batch additionally builds the filler prefix table.
#define K1_THREADS 64
#define K1_BLKS ((N + K1_THREADS - 1) / K1_THREADS)   // 313
#define MP (M / 2)                                    // 512 m-pairs

__global__ __launch_bounds__(K1_THREADS) void k_assign(
        const float* __restrict__ pts,
        const float* __restrict__ kp) {
    // sA[mp] = {pack2(kx_e,kx_o), pack2(ky_e,ky_o)}
    // sB[mp] = {pack2(kz_e,kz_o), pack2(kw_e,kw_o)}, kw = 0.5*|k|^2
    __shared__ ulonglong2 sA[MP];
    __shared__ ulonglong2 sB[MP];

    const int b = blockIdx.y;
    const float* kpb = kp + (size_t)b * M * 3;
    for (int mp = threadIdx.x; mp < MP; mp += K1_THREADS) {
        int me = 2 * mp, mo = 2 * mp + 1;
        float ex = kpb[me * 3 + 0], ey = kpb[me * 3 + 1], ez = kpb[me * 3 + 2];
        float ox = kpb[mo * 3 + 0], oy = kpb[mo * 3 + 1], oz = kpb[mo * 3 + 2];
        float ew = 0.5f * (ex * ex + ey * ey + ez * ez);
        float ow_ = 0.5f * (ox * ox + oy * oy + oz * oz);
        ulonglong2 a, c;
        a.x = pack2(ex, ox); a.y = pack2(ey, oy);
        c.x = pack2(ez, oz); c.y = pack2(ew, ow_);
        sA[mp] = a;
        sB[mp] = c;
    }
    __syncthreads();

    // Filler prefix table: S[k] = sequential sum of first k points (k<=PL).
    if (blockIdx.x == 0 && threadIdx.x == 0) {
        const float* q = pts + (size_t)b * N * 3;
        float ax = 0.f, ay = 0.f, az = 0.f;
        g_pref[b * 64 + 0] = make_float4(0.f, 0.f, 0.f, 0.f);
        for (int k = 0; k < PL; k++) {
            ax += q[3 * k + 0];
            ay += q[3 * k + 1];
            az += q[3 * k + 2];
            g_pref[b * 64 + k + 1] = make_float4(ax, ay, az, 0.f);
        }
    }

    const int p = blockIdx.x * K1_THREADS + threadIdx.x;
    float x = 0.f, y = 0.f, z = 0.f;
    if (p < N) {
        const float* q = pts + ((size_t)b * N + p) * 3;
        x = q[0]; y = q[1]; z = q[2];
    }
    unsigned long long nx2 = pack2(-x, -x);
    unsigned long long ny2 = pack2(-y, -y);
    unsigned long long nz2 = pack2(-z, -z);

    float bve = INFINITY, bvo = INFINITY;
    int bme = 0, bmo = 0;       // m-pair indices for even/odd chains

#pragma unroll 8
    for (int mp = 0; mp < MP; mp++) {
        ulonglong2 a = sA[mp];
        ulonglong2 c = sB[mp];
        unsigned long long v2;
        // v = 0.5|k|^2 - k.p  (monotone in true sq-dist for a fixed point)
        asm("fma.rn.f32x2 %0, %1, %2, %3;" : "=l"(v2) : "l"(c.x), "l"(nz2), "l"(c.y));
        asm("fma.rn.f32x2 %0, %1, %2, %3;" : "=l"(v2) : "l"(a.y), "l"(ny2), "l"(v2));
        asm("fma.rn.f32x2 %0, %1, %2, %3;" : "=l"(v2) : "l"(a.x), "l"(nx2), "l"(v2));
        float v0, v1;
        asm("mov.b64 {%0, %1}, %2;" : "=f"(v0), "=f"(v1) : "l"(v2));
        // strict <: keeps FIRST minimum within each chain (ascending m).
        bool le = v0 < bve;
        bme = le ? mp : bme;
        bve = fminf(bve, v0);
        bool lo = v1 < bvo;
        bmo = lo ? mp : bmo;
        bvo = fminf(bvo, v1);
    }

    if (p < N) {
        // Merge chains. Global first-min: odd wins only if strictly smaller, or
        // equal with smaller m (2*bmo+1 < 2*bme only if bmo < bme).
        int me = 2 * bme, mo = 2 * bmo + 1;
        bool ow2 = (bvo < bve) || (bvo == bve && mo < me);
        float bestv = ow2 ? bvo : bve;
        int bestm = ow2 ? mo : me;

        int gi = b * N + p;
        int bm = b * M + bestm;
        float pp = x * x + y * y + z * z;
        float dist = fmaf(2.0f, bestv, pp);      // true squared distance
        g_p2n[gi] = bestm;
        // coordinate sums (no-return atomics -> RED.ADD)
        atomicAdd(&g_sumx[bm], x);
        atomicAdd(&g_sumy[bm], y);
        atomicAdd(&g_sumz[bm], z);
        int pos = atomicAdd(&g_count[bm], 1);
        if (pos < L_CAP) {
            g_lidx[(size_t)bm * L_CAP + pos] = p;
            g_ldst[(size_t)bm * L_CAP + pos] = dist;
        }
    }
}

// ---------------- k_select: one WARP per (b, m), fused final reduce ---------
#define SEL_THREADS 256
#define SEL_WARPS (SEL_THREADS / 32)      // 8
#define SEL_BLOCKS (B * M / SEL_WARPS)    // 512
#define SLOTS (L_CAP / 32)                // 6 keys per lane

__global__ __launch_bounds__(SEL_THREADS) void k_select(
        const float* __restrict__ pts,
        const float* __restrict__ kpw,
        const float* __restrict__ pose,
        const float* __restrict__ ow,
        float* __restrict__ out) {
    __shared__ float s_a[SEL_WARPS];
    __shared__ float s_w[SEL_WARPS];
    __shared__ int s_last;

    int wg = (blockIdx.x * SEL_THREADS + threadIdx.x) >> 5;   // global warp id
    int wid = threadIdx.x >> 5;
    int lane = threadIdx.x & 31;
    int b = wg / M;
    int m = wg - b * M;
    int i = wg;

    const float* ptsb = pts + (size_t)b * N * 3;
    const int* p2nb = g_p2n + (size_t)b * N;

    // Independent loads up front (all L2-resident from k_assign's writes).
    int c = g_count[i];
    float ssx = g_sumx[i];
    float ssy = g_sumy[i];
    float ssz = g_sumz[i];
    int pv0 = p2nb[lane];              // first filler window
    int pv1 = p2nb[lane + 32];         // second window (fill <= 50 < 64)

    if (lane == 0) {                   // self-reset for next replay
        g_count[i] = 0;
        g_sumx[i] = 0.f; g_sumy[i] = 0.f; g_sumz[i] = 0.f;
    }

    float sx = 0.f, sy = 0.f, sz = 0.f;
    int fill;

    if (c <= PL) {
        // Sum already computed by k_assign's RED.ADD — no gather needed.
        if (lane == 0) { sx = ssx; sy = ssy; sz = ssz; }
        fill = PL - c;
        // FAST PATH: if no index < fill is assigned to m, the fillers are
        // exactly points 0..fill-1 -> one prefix-table load. (~95% of warps.)
        if (fill > 0) {
            unsigned mm0 = __ballot_sync(0xffffffffu, pv0 == m);
            unsigned mm1 = __ballot_sync(0xffffffffu, pv1 == m);
            unsigned long long matches =
                ((unsigned long long)mm1 << 32) | mm0;
            unsigned long long below = (1ull << fill) - 1ull;   // fill <= 50
            if ((matches & below) == 0ull) {
                if (lane == 0) {
                    float4 S = g_pref[b * 64 + fill];
                    sx += S.x; sy += S.y; sz += S.z;
                }
                fill = 0;
            }
        }
    } else {
        // RANK selection: key = (enc(dist)<<32)|idx is unique => total order
        // => rank(k) = #{k' < k}; rank < 50 is EXACTLY the stable top_k set.
        const int* lidx = g_lidx + (size_t)i * L_CAP;
        const float* ldst = g_ldst + (size_t)i * L_CAP;
        int cc = min(c, L_CAP);
        int su = (cc + 31) >> 5;       // slot rounds holding real keys

        unsigned long long ks[SLOTS];
#pragma unroll
        for (int t = 0; t < SLOTS; t++) {
            int j = lane + 32 * t;
            unsigned long long key = ~0ull;         // sentinel = +inf
            if (j < cc) {
                float d = ldst[j];
                unsigned u = __float_as_uint(d);
                unsigned enc = (u & 0x80000000u) ? ~u : (u | 0x80000000u);
                key = ((unsigned long long)enc << 32) | (unsigned)lidx[j];
            }
            ks[t] = key;
        }

        unsigned cnt[SLOTS] = {0, 0, 0, 0, 0, 0};
        for (int t2 = 0; t2 < su; t2++) {
            unsigned long long kslot = ks[t2];
#pragma unroll 4
            for (int src = 0; src < 32; src++) {
                unsigned long long kk =
                    __shfl_sync(0xffffffffu, kslot, src);
#pragma unroll
                for (int t = 0; t < SLOTS; t++) cnt[t] += (kk < ks[t]);
            }
        }

        // Gather selected points (exactly 50 across the warp, <=6 per lane).
#pragma unroll
        for (int t = 0; t < SLOTS; t++) {
            if (cnt[t] < PL) {
                unsigned idx = (unsigned)ks[t];
                const float* q = &ptsb[(size_t)idx * 3];
                sx += q[0]; sy += q[1]; sz += q[2];
            }
        }
        fill = 0;
    }

    // Fallback fillers: first (50 - c) point indices with p2n != m (FAR pad,
    // stable tie-break = ascending index). Warp-cooperative ballot sweep.
    int n0 = 0;
    while (fill > 0) {
        int n = n0 + lane;                 // n stays far below N (fill <= 50)
        int pn = (n0 == 0) ? pv0 : ((n0 == 32) ? pv1 : p2nb[n]);
        bool ok = (pn != m);
        unsigned msk = __ballot_sync(0xffffffffu, ok);
        int rank = __popc(msk & ((1u << lane) - 1u));
        if (ok && rank < fill) {
            const float* q = &ptsb[(size_t)n * 3];
            sx += q[0]; sy += q[1]; sz += q[2];
        }
        fill -= min(fill, __popc(msk));
        n0 += 32;
    }

    // Warp reduce
#pragma unroll
    for (int off = 16; off; off >>= 1) {
        sx += __shfl_xor_sync(0xffffffffu, sx, off);
        sy += __shfl_xor_sync(0xffffffffu, sy, off);
        sz += __shfl_xor_sync(0xffffffffu, sz, off);
    }

    if (lane == 0) {
        // mean(R p + t) = R mean(p) + t
        const float* P = pose + b * 16;
        float mx = sx * (1.0f / PL), my = sy * (1.0f / PL), mz = sz * (1.0f / PL);
        float ex = P[0] * mx + P[1] * my + P[2]  * mz + P[3]  - kpw[i * 3 + 0];
        float ey = P[4] * mx + P[5] * my + P[6]  * mz + P[7]  - kpw[i * 3 + 1];
        float ez = P[8] * mx + P[9] * my + P[10] * mz + P[11] - kpw[i * 3 + 2];
        float w = ow[i];
        s_a[wid] = w * (fabsf(ex) + fabsf(ey) + fabsf(ez));
        s_w[wid] = w;
    }
    __syncthreads();

    // One plain store per block, then single ticket (proven best in R14);
    // last block reduces partials.
    if (threadIdx.x == 0) {
        float ba = 0.f, bw = 0.f;
#pragma unroll
        for (int k = 0; k < SEL_WARPS; k++) { ba += s_a[k]; bw += s_w[k]; }
        g_partA[blockIdx.x] = ba;
        g_partW[blockIdx.x] = bw;
        __threadfence();
        int t = atomicAdd(&g_done, 1);
        s_last = (t == SEL_BLOCKS - 1);
    }
    __syncthreads();

    if (s_last) {
        __threadfence();
        float a = 0.f, w = 0.f;
        for (int k = threadIdx.x; k < SEL_BLOCKS; k += SEL_THREADS) {
            a += g_partA[k];
            w += g_partW[k];
        }
#pragma unroll
        for (int off = 16; off; off >>= 1) {
            a += __shfl_xor_sync(0xffffffffu, a, off);
            w += __shfl_xor_sync(0xffffffffu, w, off);
        }
        if (lane == 0) { s_a[wid] = a; s_w[wid] = w; }
        __syncthreads();
        if (threadIdx.x == 0) {
            double A = 0.0, W = 0.0;
#pragma unroll
            for (int k = 0; k < SEL_WARPS; k++) { A += s_a[k]; W += s_w[k]; }
            if (W < 1e-6) W = 1e-6;
            out[0] = (float)(A / W);
            g_done = 0;                 // self-reset for next replay
            __threadfence();
        }
    }
}

extern "C" void kernel_launch(void* const* d_in, const int* in_sizes, int n_in,
                              void* d_out, int out_size) {
    const float* pts  = (const float*)d_in[0];  // (B, N, 3)
    const float* kp   = (const float*)d_in[1];  // (B, M, 3)
    const float* kpw  = (const float*)d_in[2];  // (B, M, 3)
    const float* pose = (const float*)d_in[3];  // (B, 4, 4)
    const float* ow   = (const float*)d_in[4];  // (B, M)
    float* out = (float*)d_out;

    dim3 g1(K1_BLKS, B);
    k_assign<<<g1, K1_THREADS>>>(pts, kp);

    k_select<<<SEL_BLOCKS, SEL_THREADS>>>(pts, kpw, pose, ow, out);
}